// round 6
// baseline (speedup 1.0000x reference)
#include <cuda_runtime.h>
#include <cstdint>

#define ITEMS_TOTAL 50000
#define DIM         64
#define BATCH       16
#define VEC4_PER_ROW (DIM / 4)   // 16 float4 per row
#define NPG         50
#define ROWS_PER_CTA 64
#define THREADS      512         // 32 row-slots x 16 lanes; each thread: 2 rows

// Single fused kernel: broadcast emb_table to all 16 batch slices with the
// gated update blended in for touched rows. Each thread owns 2 rows' worth of
// one float4 lane (2 loads + 32 independent streaming stores for max MLP).
__global__ void __launch_bounds__(THREADS)
fused_kernel(const float4* __restrict__ emb4,
             const float*  __restrict__ feat,      // (BATCH*NPG, DIM)
             const float*  __restrict__ alpha,     // (ITEMS_TOTAL, 1)
             const void*   __restrict__ nodes_raw, // int32 or int64, 800 entries
             float4*       __restrict__ out4) {    // (BATCH, ITEMS_TOTAL, DIM/4)
    __shared__ int s_stage[BATCH * NPG];            // raw first 3200 bytes
    __shared__ int s_idx[BATCH * NPG];              // node indices as int32
    __shared__ int s_pos[ROWS_PER_CTA][BATCH + 1];  // last pos per (row,b); pad
    __shared__ int s_not64;
    __shared__ int s_any;

    const int tid   = threadIdx.x;
    const int rslot = tid >> 4;                     // 0..31
    const int b_id  = tid & 15;                     // batch / lane
    const int row_base = blockIdx.x * ROWS_PER_CTA;
    const int row0 = row_base + rslot;              // rows: rslot and rslot+32
    const int row1 = row0 + 32;
    const bool ok0 = (row0 < ITEMS_TOTAL);
    const bool ok1 = (row1 < ITEMS_TOTAL);

    // ---- Prefetch emb chunks (independent of smem phases) ----
    const long long n4 = (long long)ITEMS_TOTAL * VEC4_PER_ROW;   // 800,000
    const long long t0 = (long long)row0 * VEC4_PER_ROW + b_id;
    const long long t1 = (long long)row1 * VEC4_PER_ROW + b_id;
    float4 v0, v1;
    if (ok0) v0 = emb4[t0];
    if (ok1) v1 = emb4[t1];

    const int* a32 = (const int*)nodes_raw;
    if (tid == 0) { s_not64 = 0; s_any = 0; }

    // Phase 1a: stage first 3200 bytes (valid under both dtypes).
    for (int k = tid; k < BATCH * NPG; k += THREADS) s_stage[k] = a32[k];
    __syncthreads();

    // Phase 1b: dtype detection — int64 LE values < 50000 => high words zero.
    for (int k = tid; k < 400; k += THREADS) {
        if (s_stage[2 * k + 1] != 0) s_not64 = 1;   // benign race
    }
    __syncthreads();
    const bool is64 = (s_not64 == 0);

    // Phase 1c: compact to int32; flag if any node hits this CTA's window.
    for (int k = tid; k < BATCH * NPG; k += THREADS) {
        int val;
        if (is64) {
            val = (k < 400) ? s_stage[2 * k] : a32[2 * k];  // int64 buf = 6400 B
        } else {
            val = s_stage[k];
        }
        s_idx[k] = val;
        if ((unsigned)(val - row_base) < (unsigned)ROWS_PER_CTA) s_any = 1;
    }
    __syncthreads();

    if (s_any) {
        // Phase 2: thread (rslot, b) scans graph b for both of its rows.
        const int base = b_id * NPG;
        int p0 = -1, p1 = -1;
#pragma unroll 10
        for (int jj = 0; jj < NPG; jj++) {
            int nidx = s_idx[base + jj];
            if (nidx == row0) p0 = base + jj;   // forward scan => last wins
            if (nidx == row1) p1 = base + jj;
        }
        s_pos[rslot][b_id]      = p0;
        s_pos[rslot + 32][b_id] = p1;
        __syncthreads();

#pragma unroll
        for (int half = 0; half < 2; half++) {
            const int  rr  = rslot + half * 32;
            const bool ok  = half ? ok1 : ok0;
            if (!ok) continue;
            const float4 v = half ? v1 : v0;
            const long long t = half ? t1 : t0;
            const int row = half ? row1 : row0;

            bool touched = false;
#pragma unroll
            for (int b = 0; b < BATCH; b++) touched |= (s_pos[rr][b] >= 0);

            if (!touched) {
#pragma unroll
                for (int b = 0; b < BATCH; b++)
                    __stcs(&out4[(long long)b * n4 + t], v);
            } else {
                const float a  = alpha[row];
                const float na = 1.0f - a;
#pragma unroll
                for (int b = 0; b < BATCH; b++) {
                    float4 w = v;
                    int p = s_pos[rr][b];
                    if (p >= 0) {
                        const float4* f4 = reinterpret_cast<const float4*>(
                            feat + (long long)p * DIM);
                        float4 f = f4[b_id];
                        w.x = fmaf(a, f.x, na * v.x);
                        w.y = fmaf(a, f.y, na * v.y);
                        w.z = fmaf(a, f.z, na * v.z);
                        w.w = fmaf(a, f.w, na * v.w);
                    }
                    __stcs(&out4[(long long)b * n4 + t], w);
                }
            }
        }
    } else {
        // Untouched CTA: pure 16-way broadcast stores, 32 per thread in flight.
        if (ok0) {
#pragma unroll
            for (int b = 0; b < BATCH; b++)
                __stcs(&out4[(long long)b * n4 + t0], v0);
        }
        if (ok1) {
#pragma unroll
            for (int b = 0; b < BATCH; b++)
                __stcs(&out4[(long long)b * n4 + t1], v1);
        }
    }
}

extern "C" void kernel_launch(void* const* d_in, const int* in_sizes, int n_in,
                              void* d_out, int out_size) {
    // 0: nodes (int32/int64)  1: nodes_output f32  2: emb_table f32  3: alpha f32
    const void*  nodes = d_in[0];
    const float* feat  = (const float*)d_in[1];
    const float* emb   = (const float*)d_in[2];
    const float* alpha = (const float*)d_in[3];
    float*       out   = (float*)d_out;

    const int blocks = (ITEMS_TOTAL + ROWS_PER_CTA - 1) / ROWS_PER_CTA;  // 782
    fused_kernel<<<blocks, THREADS>>>(
        reinterpret_cast<const float4*>(emb), feat, alpha, nodes,
        reinterpret_cast<float4*>(out));
}

// round 8
// speedup vs baseline: 1.0453x; 1.0453x over previous
#include <cuda_runtime.h>
#include <cstdint>

#define ITEMS_TOTAL 50000
#define DIM         64
#define BATCH       16
#define NPG         50
#define VEC4_PER_ROW (DIM / 4)   // 16 float4 per row
#define ROWS_PER_CTA 32
#define THREADS      512         // 32 rows x 16 lanes

// Single fused kernel (R5 structure — best known): broadcast emb_table to all
// 16 batch slices, blending the gated update for touched rows. Node
// bookkeeping recomputed per-CTA in shared memory; emb read prefetched ahead
// of the prologue. Prologue staging + dtype detection fused into one pass.
__global__ void __launch_bounds__(THREADS)
fused_kernel(const float4* __restrict__ emb4,
             const float*  __restrict__ feat,      // (BATCH*NPG, DIM)
             const float*  __restrict__ alpha,     // (ITEMS_TOTAL, 1)
             const void*   __restrict__ nodes_raw, // int32 or int64, 800 entries
             float4*       __restrict__ out4) {    // (BATCH, ITEMS_TOTAL, DIM/4)
    __shared__ int s_stage[BATCH * NPG];            // raw first 3200 bytes
    __shared__ int s_idx[BATCH * NPG];              // node indices as int32
    __shared__ int s_pos[ROWS_PER_CTA][BATCH + 1];  // last pos per (row,b); pad
    __shared__ int s_not64;
    __shared__ int s_any;                           // any node in this CTA's rows?

    const int tid  = threadIdx.x;
    const int r    = tid >> 4;                      // 0..31 local row
    const int b_id = tid & 15;                      // 0..15 batch / lane
    const int row  = blockIdx.x * ROWS_PER_CTA + r;
    const int row_base = blockIdx.x * ROWS_PER_CTA;
    const bool row_ok = (row < ITEMS_TOTAL);

    // ---- Prefetch emb row chunk (independent of smem phases) ----
    const long long n4 = (long long)ITEMS_TOTAL * VEC4_PER_ROW;   // 800,000
    const long long t  = (long long)row * VEC4_PER_ROW + b_id;
    float4 v;
    if (row_ok) v = emb4[t];

    const int* a32 = (const int*)nodes_raw;
    if (tid == 0) { s_not64 = 0; s_any = 0; }
    // tid==0's flag writes race with the detection below only benignly:
    // all other writers store 1; a CTA-wide __syncthreads follows before reads.
    __syncthreads();

    // Phase 1: stage first 3200 bytes AND detect dtype in the same pass.
    // int64 LE with values < 50000 => every odd 32-bit word is zero.
    for (int k = tid; k < BATCH * NPG; k += THREADS) {
        int w = a32[k];
        s_stage[k] = w;
        if ((k & 1) && w != 0) s_not64 = 1;         // benign race
    }
    __syncthreads();
    const bool is64 = (s_not64 == 0);

    // Phase 2: compact to int32; flag if any node hits this CTA's window.
    for (int k = tid; k < BATCH * NPG; k += THREADS) {
        int val;
        if (is64) {
            val = (k < 400) ? s_stage[2 * k] : a32[2 * k];  // int64 buf = 6400 B
        } else {
            val = s_stage[k];
        }
        s_idx[k] = val;
        if ((unsigned)(val - row_base) < (unsigned)ROWS_PER_CTA) s_any = 1;
    }
    __syncthreads();

    if (s_any) {
        // Phase 3: thread (r, b) finds last occurrence of its row in graph b.
        int p = -1;
        const int base = b_id * NPG;
#pragma unroll 10
        for (int jj = 0; jj < NPG; jj++) {
            if (s_idx[base + jj] == row) p = base + jj;  // forward scan => last
        }
        s_pos[r][b_id] = p;
        __syncthreads();

        if (row_ok) {
            bool touched = false;
#pragma unroll
            for (int b = 0; b < BATCH; b++) touched |= (s_pos[r][b] >= 0);

            if (!touched) {
#pragma unroll
                for (int b = 0; b < BATCH; b++)
                    __stcs(&out4[(long long)b * n4 + t], v);
            } else {
                const float a  = alpha[row];
                const float na = 1.0f - a;
#pragma unroll
                for (int b = 0; b < BATCH; b++) {
                    float4 w = v;
                    int p2 = s_pos[r][b];
                    if (p2 >= 0) {
                        const float4* f4 = reinterpret_cast<const float4*>(
                            feat + (long long)p2 * DIM);
                        float4 f = f4[b_id];
                        w.x = fmaf(a, f.x, na * v.x);
                        w.y = fmaf(a, f.y, na * v.y);
                        w.z = fmaf(a, f.z, na * v.z);
                        w.w = fmaf(a, f.w, na * v.w);
                    }
                    __stcs(&out4[(long long)b * n4 + t], w);
                }
            }
        }
    } else if (row_ok) {
        // Untouched CTA: pure 16-way broadcast store.
#pragma unroll
        for (int b = 0; b < BATCH; b++)
            __stcs(&out4[(long long)b * n4 + t], v);
    }
}

extern "C" void kernel_launch(void* const* d_in, const int* in_sizes, int n_in,
                              void* d_out, int out_size) {
    // 0: nodes (int32/int64)  1: nodes_output f32  2: emb_table f32  3: alpha f32
    const void*  nodes = d_in[0];
    const float* feat  = (const float*)d_in[1];
    const float* emb   = (const float*)d_in[2];
    const float* alpha = (const float*)d_in[3];
    float*       out   = (float*)d_out;

    const int blocks = (ITEMS_TOTAL + ROWS_PER_CTA - 1) / ROWS_PER_CTA;  // 1563
    fused_kernel<<<blocks, THREADS>>>(
        reinterpret_cast<const float4*>(emb), feat, alpha, nodes,
        reinterpret_cast<float4*>(out));
}

// round 9
// speedup vs baseline: 1.0559x; 1.0101x over previous
#include <cuda_runtime.h>
#include <cstdint>

#define ITEMS_TOTAL 50000
#define DIM         64
#define BATCH       16
#define NPG         50
#define VEC4_PER_ROW (DIM / 4)   // 16 float4 per row
#define ROWS_PER_CTA 32
#define THREADS      512         // 32 rows x 16 lanes

// Single fused kernel: broadcast emb_table to all 16 batch slices, blending
// the gated update for touched rows. Node bookkeeping recomputed per-CTA in
// shared memory; emb read prefetched ahead of the prologue to hide it.
// (Byte-identical revert to the R5 kernel that measured 33.28 us.)
__global__ void __launch_bounds__(THREADS)
fused_kernel(const float4* __restrict__ emb4,
             const float*  __restrict__ feat,      // (BATCH*NPG, DIM)
             const float*  __restrict__ alpha,     // (ITEMS_TOTAL, 1)
             const void*   __restrict__ nodes_raw, // int32 or int64, 800 entries
             float4*       __restrict__ out4) {    // (BATCH, ITEMS_TOTAL, DIM/4)
    __shared__ int s_stage[BATCH * NPG];            // raw first 3200 bytes
    __shared__ int s_idx[BATCH * NPG];              // node indices as int32
    __shared__ int s_pos[ROWS_PER_CTA][BATCH + 1];  // last pos per (row,b); pad
    __shared__ int s_not64;
    __shared__ int s_any;                           // any node in this CTA's rows?

    const int tid  = threadIdx.x;
    const int r    = tid >> 4;                      // 0..31 local row
    const int b_id = tid & 15;                      // 0..15 batch / lane
    const int row  = blockIdx.x * ROWS_PER_CTA + r;
    const int row_base = blockIdx.x * ROWS_PER_CTA;
    const bool row_ok = (row < ITEMS_TOTAL);

    // ---- Prefetch emb row chunk (independent of smem phases) ----
    const long long n4 = (long long)ITEMS_TOTAL * VEC4_PER_ROW;   // 800,000
    const long long t  = (long long)row * VEC4_PER_ROW + b_id;
    float4 v;
    if (row_ok) v = emb4[t];

    const int* a32 = (const int*)nodes_raw;
    if (tid == 0) { s_not64 = 0; s_any = 0; }

    // Phase 1a: stage first 3200 bytes (valid under both dtypes).
    for (int k = tid; k < BATCH * NPG; k += THREADS) s_stage[k] = a32[k];
    __syncthreads();

    // Phase 1b: dtype detection — int64 LE with values < 50000 has all-zero
    // high words in the first 400 pairs.
    for (int k = tid; k < 400; k += THREADS) {
        if (s_stage[2 * k + 1] != 0) s_not64 = 1;   // benign race
    }
    __syncthreads();
    const bool is64 = (s_not64 == 0);

    // Phase 1c: compact to int32 indices; flag if any falls in our row window.
    for (int k = tid; k < BATCH * NPG; k += THREADS) {
        int val;
        if (is64) {
            val = (k < 400) ? s_stage[2 * k] : a32[2 * k];  // int64 buf = 6400 B
        } else {
            val = s_stage[k];
        }
        s_idx[k] = val;
        if ((unsigned)(val - row_base) < (unsigned)ROWS_PER_CTA) s_any = 1;
    }
    __syncthreads();

    if (s_any) {
        // Phase 2: thread (r, b) finds last occurrence of its row in graph b.
        int p = -1;
        const int base = b_id * NPG;
#pragma unroll 10
        for (int jj = 0; jj < NPG; jj++) {
            if (s_idx[base + jj] == row) p = base + jj;  // forward scan => last
        }
        s_pos[r][b_id] = p;
        __syncthreads();

        if (row_ok) {
            bool touched = false;
#pragma unroll
            for (int b = 0; b < BATCH; b++) touched |= (s_pos[r][b] >= 0);

            if (!touched) {
#pragma unroll
                for (int b = 0; b < BATCH; b++)
                    __stcs(&out4[(long long)b * n4 + t], v);
            } else {
                const float a  = alpha[row];
                const float na = 1.0f - a;
#pragma unroll
                for (int b = 0; b < BATCH; b++) {
                    float4 w = v;
                    int p2 = s_pos[r][b];
                    if (p2 >= 0) {
                        const float4* f4 = reinterpret_cast<const float4*>(
                            feat + (long long)p2 * DIM);
                        float4 f = f4[b_id];
                        w.x = fmaf(a, f.x, na * v.x);
                        w.y = fmaf(a, f.y, na * v.y);
                        w.z = fmaf(a, f.z, na * v.z);
                        w.w = fmaf(a, f.w, na * v.w);
                    }
                    __stcs(&out4[(long long)b * n4 + t], w);
                }
            }
        }
    } else if (row_ok) {
        // Untouched CTA: pure 16-way broadcast store.
#pragma unroll
        for (int b = 0; b < BATCH; b++)
            __stcs(&out4[(long long)b * n4 + t], v);
    }
}

extern "C" void kernel_launch(void* const* d_in, const int* in_sizes, int n_in,
                              void* d_out, int out_size) {
    // 0: nodes (int32/int64)  1: nodes_output f32  2: emb_table f32  3: alpha f32
    const void*  nodes = d_in[0];
    const float* feat  = (const float*)d_in[1];
    const float* emb   = (const float*)d_in[2];
    const float* alpha = (const float*)d_in[3];
    float*       out   = (float*)d_out;

    const int blocks = (ITEMS_TOTAL + ROWS_PER_CTA - 1) / ROWS_PER_CTA;  // 1563
    fused_kernel<<<blocks, THREADS>>>(
        reinterpret_cast<const float4*>(emb), feat, alpha, nodes,
        reinterpret_cast<float4*>(out));
}